// round 1
// baseline (speedup 1.0000x reference)
#include <cuda_runtime.h>
#include <cuda_bf16.h>

// CIN layer: B=1024, F0=32, E=64, K=128 per layer, half-split feeding forward.
//
// Decomposition:
//   hidden_{l+1}[b,j,e] (j<64)  -- dense per-e GEMM with on-the-fly A = x_i * h_j
//   out direct halves:  sum_e cur = <W_k , S[b]>  with S[b,i,j] = sum_e x[b,i,e]*h[b,j,e]
//
// Scratch hidden tensors live in __device__ globals (no allocation).

#define B_SZ   1024
#define F0     32
#define E_SZ   64
#define K_SZ   128
#define HALF   64

__device__ float g_h1[B_SZ * HALF * E_SZ];   // [b][j][e], 16 MB
__device__ float g_h2[B_SZ * HALF * E_SZ];   // [b][j][e], 16 MB

// ---------------------------------------------------------------------------
// Hidden kernel: hout[b][k][e] = bias[k] + sum_{i<32, j<FI} x[b,i,e]*h[b,j,e]*W[(i*FI+j)*128+k]
// for k in [0,64).  M = B*E = 65536 rows, tile BM=128 x BN=64, 128 threads,
// 8x8 register blocking. A-tile never materialized: a = x_i * h_j.
// ---------------------------------------------------------------------------
template<int FI>
__global__ void __launch_bounds__(128)
cin_hidden(const float* __restrict__ x, const float* __restrict__ h,
           const float* __restrict__ W, const float* __restrict__ bias,
           float* __restrict__ hout)
{
    extern __shared__ float sm[];
    float* xs = sm;                         // [128][33]   (m-major, padded)
    float* hs = sm + 128 * 33;              // [128][FI+1] (m-major, padded)
    float* ws = hs + 128 * (FI + 1);        // [FI][68]    (j-major, padded, 16B-aligned rows)

    const int tid = threadIdx.x;
    const int tx  = tid & 7;                // k-group (8 groups x 8 k = 64)
    const int ty  = tid >> 3;               // m-group (16 groups x 8 m = 128)
    const int m0  = blockIdx.x * 128;

    // load x tile: xs[mr][i]
    for (int idx = tid; idx < 128 * 32; idx += 128) {
        int i = idx >> 7, mr = idx & 127;
        int m = m0 + mr, b = m >> 6, e = m & 63;
        xs[mr * 33 + i] = x[(b * 32 + i) * 64 + e];
    }
    // load h tile: hs[mr][j]
    for (int idx = tid; idx < 128 * FI; idx += 128) {
        int j = idx >> 7, mr = idx & 127;
        int m = m0 + mr, b = m >> 6, e = m & 63;
        hs[mr * (FI + 1) + j] = h[(b * FI + j) * 64 + e];
    }

    float acc[8][8];
#pragma unroll
    for (int mm = 0; mm < 8; ++mm)
#pragma unroll
        for (int nn = 0; nn < 8; ++nn) acc[mm][nn] = 0.f;

    for (int i = 0; i < 32; ++i) {
        __syncthreads();  // protects ws reuse (and initial xs/hs load at i=0)
        // stage W chunk for this i: ws[j][k], k<64, vectorized
        for (int idx = tid; idx < FI * 16; idx += 128) {
            int j = idx >> 4, kq = idx & 15;
            float4 w = *reinterpret_cast<const float4*>(W + (i * FI + j) * 128 + kq * 4);
            *reinterpret_cast<float4*>(&ws[j * 68 + kq * 4]) = w;
        }
        __syncthreads();

        float xr[8];
#pragma unroll
        for (int mm = 0; mm < 8; ++mm) xr[mm] = xs[(ty * 8 + mm) * 33 + i];

#pragma unroll 4
        for (int j = 0; j < FI; ++j) {
            float hr[8], wv[8], p[8];
#pragma unroll
            for (int mm = 0; mm < 8; ++mm) hr[mm] = hs[(ty * 8 + mm) * (FI + 1) + j];
#pragma unroll
            for (int nn = 0; nn < 8; ++nn) wv[nn] = ws[j * 68 + tx * 8 + nn];
#pragma unroll
            for (int mm = 0; mm < 8; ++mm) p[mm] = xr[mm] * hr[mm];
#pragma unroll
            for (int mm = 0; mm < 8; ++mm)
#pragma unroll
                for (int nn = 0; nn < 8; ++nn) acc[mm][nn] += p[mm] * wv[nn];
        }
    }

    float bv[8];
#pragma unroll
    for (int nn = 0; nn < 8; ++nn) bv[nn] = bias[tx * 8 + nn];
#pragma unroll
    for (int mm = 0; mm < 8; ++mm) {
        int m = m0 + ty * 8 + mm, b = m >> 6, e = m & 63;
#pragma unroll
        for (int nn = 0; nn < 8; ++nn) {
            int k = tx * 8 + nn;
            hout[(b * HALF + k) * 64 + e] = acc[mm][nn] + bv[nn];
        }
    }
}

// ---------------------------------------------------------------------------
// S + direct kernel: for NB=8 batches per CTA,
//   S[bb][i][j] = sum_e x[b,i,e]*h[b,j,e]        (phase 1, in smem)
//   out[b, outoff+k] = 64*bias[koff+k] + sum_t S[bb][t]*W[t*128+koff+k]  (phase 2)
// ---------------------------------------------------------------------------
template<int FI, int KOUT>
__global__ void __launch_bounds__(256)
cin_sd(const float* __restrict__ x, const float* __restrict__ h,
       const float* __restrict__ W, const float* __restrict__ bias,
       float* __restrict__ out, int koff, int outoff)
{
    constexpr int NB  = 8;
    constexpr int FAN = 32 * FI;
    extern __shared__ float sm[];
    float* xs  = sm;                    // 32*64
    float* hs  = xs + 2048;             // FI*65
    float* Ss  = hs + FI * 65;          // NB * FAN
    float* red = Ss + NB * FAN;         // 256*4

    const int tid = threadIdx.x;
    const int b0  = blockIdx.x * NB;

    // phase 1: per-batch S
    for (int bb = 0; bb < NB; ++bb) {
        int b = b0 + bb;
        __syncthreads();
        for (int idx = tid; idx < 2048; idx += 256) xs[idx] = x[b * 2048 + idx];
        for (int idx = tid; idx < FI * 64; idx += 256) {
            int j = idx >> 6, e = idx & 63;
            hs[j * 65 + e] = h[(b * FI + j) * 64 + e];
        }
        __syncthreads();

        constexpr int TJ = FI / 4;          // j groups of 4
        if (tid < 16 * TJ) {                // 16 i-groups of 2
            int tig = tid / TJ, tjg = tid % TJ;
            float a[2][4] = {{0.f,0.f,0.f,0.f},{0.f,0.f,0.f,0.f}};
            for (int e = 0; e < 64; ++e) {
                float x0 = xs[(tig * 2 + 0) * 64 + e];
                float x1 = xs[(tig * 2 + 1) * 64 + e];
#pragma unroll
                for (int dj = 0; dj < 4; ++dj) {
                    float hv = hs[(tjg * 4 + dj) * 65 + e];
                    a[0][dj] += x0 * hv;
                    a[1][dj] += x1 * hv;
                }
            }
#pragma unroll
            for (int di = 0; di < 2; ++di)
#pragma unroll
                for (int dj = 0; dj < 4; ++dj)
                    Ss[bb * FAN + (tig * 2 + di) * FI + (tjg * 4 + dj)] = a[di][dj];
        }
    }
    __syncthreads();

    // phase 2: out = S . W  (t-split across P parts, float4 W loads)
    constexpr int NKV = KOUT / 4;
    constexpr int P   = 256 / NKV;
    constexpr int TP  = FAN / P;
    const int p  = tid / NKV;
    const int kq = tid % NKV;

    float4 acc[NB];
#pragma unroll
    for (int bb = 0; bb < NB; ++bb) acc[bb] = make_float4(0.f, 0.f, 0.f, 0.f);

    for (int t = p * TP; t < (p + 1) * TP; ++t) {
        float4 w = *reinterpret_cast<const float4*>(W + t * 128 + koff + kq * 4);
#pragma unroll
        for (int bb = 0; bb < NB; ++bb) {
            float s = Ss[bb * FAN + t];
            acc[bb].x += s * w.x;
            acc[bb].y += s * w.y;
            acc[bb].z += s * w.z;
            acc[bb].w += s * w.w;
        }
    }

    for (int bb = 0; bb < NB; ++bb) {
        __syncthreads();
        reinterpret_cast<float4*>(red)[tid] = acc[bb];
        __syncthreads();
        if (tid < KOUT) {
            int k = tid;
            float s = 0.f;
#pragma unroll
            for (int pp = 0; pp < P; ++pp)
                s += red[(pp * NKV + (k >> 2)) * 4 + (k & 3)];
            out[(b0 + bb) * 256 + outoff + k] = s + 64.0f * bias[koff + k];
        }
    }
}

// ---------------------------------------------------------------------------
extern "C" void kernel_launch(void* const* d_in, const int* in_sizes, int n_in,
                              void* d_out, int out_size)
{
    const float* x  = (const float*)d_in[0];
    const float* W0 = (const float*)d_in[1];
    const float* b0 = (const float*)d_in[2];
    const float* W1 = (const float*)d_in[3];
    const float* b1 = (const float*)d_in[4];
    const float* W2 = (const float*)d_in[5];
    const float* b2 = (const float*)d_in[6];
    float* out = (float*)d_out;

    float *h1p, *h2p;
    cudaGetSymbolAddress((void**)&h1p, g_h1);
    cudaGetSymbolAddress((void**)&h2p, g_h2);

    const int smH32 = (128 * 33 + 128 * 33 + 32 * 68) * 4;                   // 42.5 KB
    const int smH64 = (128 * 33 + 128 * 65 + 64 * 68) * 4;                   // 67.6 KB
    const int smS32 = (2048 + 32 * 65 + 8 * 1024 + 1024) * 4;                // 53.4 KB
    const int smS64 = (2048 + 64 * 65 + 8 * 2048 + 1024) * 4;                // 94.5 KB

    cudaFuncSetAttribute(cin_hidden<32>, cudaFuncAttributeMaxDynamicSharedMemorySize, smH32);
    cudaFuncSetAttribute(cin_hidden<64>, cudaFuncAttributeMaxDynamicSharedMemorySize, smH64);
    cudaFuncSetAttribute(cin_sd<32, 64>, cudaFuncAttributeMaxDynamicSharedMemorySize, smS32);
    cudaFuncSetAttribute(cin_sd<64, 64>, cudaFuncAttributeMaxDynamicSharedMemorySize, smS64);
    cudaFuncSetAttribute(cin_sd<64, 128>, cudaFuncAttributeMaxDynamicSharedMemorySize, smS64);

    const int nM = (B_SZ * E_SZ) / 128;   // 512 CTAs

    // hidden chain (dense per-e, lower halves)
    cin_hidden<32><<<nM, 128, smH32>>>(x, x,   W0, b0, h1p);
    cin_hidden<64><<<nM, 128, smH64>>>(x, h1p, W1, b1, h2p);

    // direct halves via S-trick
    cin_sd<32, 64 ><<<B_SZ / 8, 256, smS32>>>(x, x,   W0, b0, out, 64, 0);
    cin_sd<64, 64 ><<<B_SZ / 8, 256, smS64>>>(x, h1p, W1, b1, out, 64, 64);
    cin_sd<64, 128><<<B_SZ / 8, 256, smS64>>>(x, h2p, W2, b2, out, 0, 128);
}